// round 1
// baseline (speedup 1.0000x reference)
#include <cuda_runtime.h>
#include <cstdint>
#include <cstddef>

#define TT 511          // T-1 rows
#define VV 32000
#define EE 512
#define HH 512
#define SPLITS 25
#define KCHUNK 1280     // 32000 / 25, multiple of 16

// ---------------- scratch (__device__ globals; no allocation) ----------------
__device__ float g_part[SPLITS * 512 * 512];          // split-K partials for emb
__device__ float g_emb[TT * EE];
__device__ float g_xproj[TT * HH];
__device__ float g_hs[TT * HH];
__device__ float g_logits[(size_t)TT * VV];

// ---------------- f32x2 helpers ----------------
__device__ __forceinline__ void fma2(unsigned long long& d, unsigned long long a,
                                     unsigned long long b) {
    asm("fma.rn.f32x2 %0, %1, %2, %0;" : "+l"(d) : "l"(a), "l"(b));
}
__device__ __forceinline__ unsigned long long dup2(float x) {
    unsigned long long d;
    asm("mov.b64 %0, {%1, %1};" : "=l"(d) : "f"(x));
    return d;
}
__device__ __forceinline__ float2 unpack2(unsigned long long d) {
    float2 r;
    asm("mov.b64 {%0, %1}, %2;" : "=f"(r.x), "=f"(r.y) : "l"(d));
    return r;
}

// ---------------- 128x128 NT fp32 GEMM (C = A[M,K] * B[N,K]^T), split-K via z ----------------
__global__ void __launch_bounds__(256, 1)
gemm_nt128(const float* __restrict__ A, int lda,
           const float* __restrict__ B, int ldb,
           float* __restrict__ C, int ldc, size_t zStride,
           int M, int kLen)
{
    __shared__ float As[16][132];
    __shared__ float Bs[16][132];
    const int tid = threadIdx.x;
    const int nt = blockIdx.x, mt = blockIdx.y, sz = blockIdx.z;
    const int kOff = sz * kLen;
    float* Cz = C + (size_t)sz * zStride;
    const int ty = tid >> 4, tx = tid & 15;
    const int m0 = ty * 8, n0 = tx * 8;

    unsigned long long acc[8][4];
#pragma unroll
    for (int i = 0; i < 8; i++)
#pragma unroll
        for (int j = 0; j < 4; j++) acc[i][j] = 0ull;

    for (int kb = 0; kb < kLen; kb += 16) {
#pragma unroll
        for (int i = 0; i < 2; i++) {
            int idx = tid + i * 256;
            int m = idx >> 2;
            int k4 = (idx & 3) << 2;
            size_t gk = (size_t)(kOff + kb + k4);
            float4 va = make_float4(0.f, 0.f, 0.f, 0.f);
            int ra = mt * 128 + m;
            if (ra < M) va = *(const float4*)(A + (size_t)ra * lda + gk);
            As[k4 + 0][m] = va.x; As[k4 + 1][m] = va.y;
            As[k4 + 2][m] = va.z; As[k4 + 3][m] = va.w;
            int rb = nt * 128 + m;
            float4 vb = *(const float4*)(B + (size_t)rb * ldb + gk);
            Bs[k4 + 0][m] = vb.x; Bs[k4 + 1][m] = vb.y;
            Bs[k4 + 2][m] = vb.z; Bs[k4 + 3][m] = vb.w;
        }
        __syncthreads();
#pragma unroll
        for (int k = 0; k < 16; k++) {
            float4 a0 = *(const float4*)&As[k][m0];
            float4 a1 = *(const float4*)&As[k][m0 + 4];
            ulonglong2 b0 = *(const ulonglong2*)&Bs[k][n0];
            ulonglong2 b1 = *(const ulonglong2*)&Bs[k][n0 + 4];
            float av[8] = {a0.x, a0.y, a0.z, a0.w, a1.x, a1.y, a1.z, a1.w};
#pragma unroll
            for (int i = 0; i < 8; i++) {
                unsigned long long ad = dup2(av[i]);
                fma2(acc[i][0], ad, b0.x);
                fma2(acc[i][1], ad, b0.y);
                fma2(acc[i][2], ad, b1.x);
                fma2(acc[i][3], ad, b1.y);
            }
        }
        __syncthreads();
    }
#pragma unroll
    for (int i = 0; i < 8; i++) {
        int r = mt * 128 + m0 + i;
        if (r >= M) continue;
        float* cp = Cz + (size_t)r * ldc + nt * 128 + n0;
#pragma unroll
        for (int j = 0; j < 4; j++) {
            float2 v = unpack2(acc[i][j]);
            cp[2 * j] = v.x;
            cp[2 * j + 1] = v.y;
        }
    }
}

// ---------------- reduce split-K partials into emb ----------------
__global__ void reduce_emb_kernel()
{
    int i = blockIdx.x * 256 + threadIdx.x;
    if (i >= TT * EE) return;
    float s = 0.f;
#pragma unroll
    for (int p = 0; p < SPLITS; p++) s += g_part[p * (512 * 512) + i];
    g_emb[i] = s;
}

// ---------------- xproj = emb @ W_x^T + b  (64x64 tiles, K=512) ----------------
__global__ void __launch_bounds__(256)
xproj_kernel(const float* __restrict__ W_x, const float* __restrict__ bias)
{
    __shared__ float As[16][68];
    __shared__ float Bs[16][68];
    const int tid = threadIdx.x;
    const int nt = blockIdx.x, mt = blockIdx.y;
    const int ty = tid >> 4, tx = tid & 15;
    const int m0 = ty * 4, n0 = tx * 4;
    float acc[4][4] = {};

    for (int kb = 0; kb < 512; kb += 16) {
        int m = tid >> 2, k4 = (tid & 3) << 2;
        float4 va = make_float4(0.f, 0.f, 0.f, 0.f);
        int ra = mt * 64 + m;
        if (ra < TT) va = *(const float4*)(g_emb + (size_t)ra * 512 + kb + k4);
        As[k4 + 0][m] = va.x; As[k4 + 1][m] = va.y;
        As[k4 + 2][m] = va.z; As[k4 + 3][m] = va.w;
        float4 vb = *(const float4*)(W_x + (size_t)(nt * 64 + m) * 512 + kb + k4);
        Bs[k4 + 0][m] = vb.x; Bs[k4 + 1][m] = vb.y;
        Bs[k4 + 2][m] = vb.z; Bs[k4 + 3][m] = vb.w;
        __syncthreads();
#pragma unroll
        for (int k = 0; k < 16; k++) {
            float4 a = *(const float4*)&As[k][m0];
            float4 b = *(const float4*)&Bs[k][n0];
            float aa[4] = {a.x, a.y, a.z, a.w};
            float bb[4] = {b.x, b.y, b.z, b.w};
#pragma unroll
            for (int i = 0; i < 4; i++)
#pragma unroll
                for (int j = 0; j < 4; j++) acc[i][j] += aa[i] * bb[j];
        }
        __syncthreads();
    }
#pragma unroll
    for (int i = 0; i < 4; i++) {
        int r = mt * 64 + m0 + i;
        if (r >= TT) continue;
#pragma unroll
        for (int j = 0; j < 4; j++) {
            int col = nt * 64 + n0 + j;
            g_xproj[(size_t)r * 512 + col] = acc[i][j] + bias[col];
        }
    }
}

// ---------------- Elman recurrence: 1 cluster of 8 CTAs, W_h register-resident --------------
// Warp w of CTA c: g = w&1 selects 32-row half, s = w>>1 selects 32-wide k segment.
// lane l handles row c*64 + g*32 + l over k in [32s, 32s+32). h broadcast to all
// CTAs' SMEM via st.shared::cluster; per-step cluster barrier orders it.
__global__ void __cluster_dims__(8, 1, 1) __launch_bounds__(1024, 1)
rnn_kernel(const float* __restrict__ W_h)
{
    __shared__ float hbuf[2][512];
    __shared__ float pbuf[64][17];
    const int tid = threadIdx.x;
    const int w = tid >> 5, l = tid & 31;
    const int g = w & 1, s = w >> 1;
    const int c = (int)blockIdx.x;                 // == cluster rank (grid == 1 cluster)
    const int row = c * 64 + g * 32 + l;
    const int kbase = s * 32;

    ulonglong2 wv[8];
    {
        const ulonglong2* wp = (const ulonglong2*)(W_h + (size_t)row * 512 + kbase);
#pragma unroll
        for (int j = 0; j < 8; j++) wv[j] = wp[j];
    }
    for (int i = tid; i < 512; i += 1024) hbuf[0][i] = 0.f;

    uint32_t hbase_local = (uint32_t)__cvta_generic_to_shared(&hbuf[0][0]);
    uint32_t peer[8];
#pragma unroll
    for (int p = 0; p < 8; p++)
        asm("mapa.shared::cluster.u32 %0, %1, %2;" : "=r"(peer[p]) : "r"(hbase_local), "r"(p));

    float xp = (tid < 64) ? g_xproj[(size_t)c * 64 + tid] : 0.f;

    __syncthreads();
    asm volatile("barrier.cluster.arrive.aligned;" ::: "memory");
    asm volatile("barrier.cluster.wait.aligned;" ::: "memory");

    for (int t = 0; t < TT; t++) {
        const int cur = t & 1;
        const ulonglong2* hp = (const ulonglong2*)&hbuf[cur][kbase];
        unsigned long long acc = 0ull;
#pragma unroll
        for (int j = 0; j < 8; j++) {
            ulonglong2 hh = hp[j];
            fma2(acc, wv[j].x, hh.x);
            fma2(acc, wv[j].y, hh.y);
        }
        float2 f = unpack2(acc);
        pbuf[g * 32 + l][s] = f.x + f.y;
        __syncthreads();
        if (tid < 64) {
            float x = xp;
#pragma unroll
            for (int s2 = 0; s2 < 16; s2++) x += pbuf[tid][s2];
            float h = 1.f / (1.f + __expf(-x));
            g_hs[(size_t)t * 512 + c * 64 + tid] = h;
            uint32_t off = (uint32_t)(((cur ^ 1) * 512 + c * 64 + tid) * 4);
#pragma unroll
            for (int p = 0; p < 8; p++)
                asm volatile("st.shared::cluster.f32 [%0], %1;"
                             :: "r"(peer[p] + off), "f"(h) : "memory");
            int tn = (t + 1 < TT) ? (t + 1) : t;
            xp = g_xproj[(size_t)tn * 512 + c * 64 + tid];
        }
        asm volatile("barrier.cluster.arrive.aligned;" ::: "memory");
        asm volatile("barrier.cluster.wait.aligned;" ::: "memory");
    }
}

// ---------------- row softmax over V=32000 ----------------
__global__ void __launch_bounds__(256)
softmax_kernel(float* __restrict__ out)
{
    const int t = blockIdx.x;
    const int tid = threadIdx.x;
    const float4* r4 = (const float4*)(g_logits + (size_t)t * VV);
    float4* o4 = (float4*)(out + (size_t)t * VV);
    __shared__ float red[256];

    float mx = -3.402823466e38f;
    for (int i = tid; i < VV / 4; i += 256) {
        float4 v = r4[i];
        mx = fmaxf(mx, fmaxf(fmaxf(v.x, v.y), fmaxf(v.z, v.w)));
    }
    red[tid] = mx; __syncthreads();
    for (int o = 128; o > 0; o >>= 1) {
        if (tid < o) red[tid] = fmaxf(red[tid], red[tid + o]);
        __syncthreads();
    }
    mx = red[0]; __syncthreads();

    float sum = 0.f;
    for (int i = tid; i < VV / 4; i += 256) {
        float4 v = r4[i];
        v.x = __expf(v.x - mx); v.y = __expf(v.y - mx);
        v.z = __expf(v.z - mx); v.w = __expf(v.w - mx);
        o4[i] = v;
        sum += (v.x + v.y) + (v.z + v.w);
    }
    red[tid] = sum; __syncthreads();
    for (int o = 128; o > 0; o >>= 1) {
        if (tid < o) red[tid] += red[tid + o];
        __syncthreads();
    }
    float inv = 1.f / red[0];

    for (int i = tid; i < VV / 4; i += 256) {
        float4 v = o4[i];
        v.x *= inv; v.y *= inv; v.z *= inv; v.w *= inv;
        o4[i] = v;
    }
}

// ---------------- launch ----------------
extern "C" void kernel_launch(void* const* d_in, const int* in_sizes, int n_in,
                              void* d_out, int out_size)
{
    const float* sent = (const float*)d_in[0];
    const float* W_e  = (const float*)d_in[1];
    const float* W_x  = (const float*)d_in[2];
    const float* W_h  = (const float*)d_in[3];
    const float* W_p  = (const float*)d_in[4];
    const float* b    = (const float*)d_in[5];
    float* out = (float*)d_out;

    float *part, *hs_ptr, *logits;
    cudaGetSymbolAddress((void**)&part,   g_part);
    cudaGetSymbolAddress((void**)&hs_ptr, g_hs);
    cudaGetSymbolAddress((void**)&logits, g_logits);

    // emb partials: sent[0:511] (511x32000) @ W_e^T (32000x512), split-K=25
    gemm_nt128<<<dim3(4, 4, SPLITS), 256>>>(sent, VV, W_e, VV,
                                            part, 512, (size_t)512 * 512, TT, KCHUNK);
    reduce_emb_kernel<<<(TT * EE + 255) / 256, 256>>>();
    // xproj = emb @ W_x^T + b
    xproj_kernel<<<dim3(8, 8), 256>>>(W_x, b);
    // sequential Elman scan (single 8-CTA cluster)
    rnn_kernel<<<8, 1024>>>(W_h);
    // logits = hs @ W_p^T
    gemm_nt128<<<dim3(250, 4, 1), 256>>>(hs_ptr, 512, W_p, 512,
                                         logits, VV, 0, TT, 512);
    // preds = softmax(logits)
    softmax_kernel<<<TT, 256>>>(out);
}